// round 2
// baseline (speedup 1.0000x reference)
#include <cuda_runtime.h>
#include <math.h>

#define NN 50000
#define EE 800000

// scratch: pre[n][c][4] = {s_up, v_up.x, v_up.y, v_up.z}
//          acc[n][c][4] = {sum m_s, sum m_v.xyz}
__device__ float g_pre[(size_t)NN * 64 * 4];
__device__ float g_acc[(size_t)NN * 64 * 4];

__device__ __forceinline__ float silu(float x) {
    return x * (1.0f / (1.0f + __expf(-x)));
}

// ---------------------------------------------------------------------------
// Kernel A: node pre-transform + accumulator zeroing
// 256 threads, 32 nodes per block. thread: kk = tid&31 (cols k, k+32),
// g = tid>>5 handles nodes g*4 .. g*4+3
// ---------------------------------------------------------------------------
__global__ void k_pre(const float* __restrict__ nf,
                      const float* __restrict__ Wsu,
                      const float* __restrict__ Wvu) {
    extern __shared__ float sm[];
    float* sWs  = sm;            // 4096
    float* sWv  = sm + 4096;     // 4096
    float* sRaw = sm + 8192;     // 32 * 256

    int tid = threadIdx.x;
    for (int i = tid; i < 4096; i += 256) { sWs[i] = Wsu[i]; sWv[i] = Wvu[i]; }

    int n0 = blockIdx.x * 32;
    for (int i = tid; i < 32 * 64; i += 256) {
        int nl = i >> 6, c4 = i & 63;
        int gn = n0 + nl;
        float4 v = make_float4(0.f, 0.f, 0.f, 0.f);
        if (gn < NN) v = ((const float4*)nf)[(size_t)gn * 64 + c4];
        ((float4*)(sRaw + nl * 256))[c4] = v;
    }
    __syncthreads();

    int kk = tid & 31;
    int g  = tid >> 5;   // 0..7
    int nbase = g * 4;

    float acc[4][2][4];
#pragma unroll
    for (int a = 0; a < 4; a++)
#pragma unroll
        for (int b = 0; b < 2; b++)
#pragma unroll
            for (int q = 0; q < 4; q++) acc[a][b][q] = 0.f;

    for (int c = 0; c < 64; c++) {
        float ws0 = sWs[c * 64 + kk], ws1 = sWs[c * 64 + kk + 32];
        float wv0 = sWv[c * 64 + kk], wv1 = sWv[c * 64 + kk + 32];
#pragma unroll
        for (int a = 0; a < 4; a++) {
            const float* row = sRaw + (nbase + a) * 256;
            float sv = row[c];
            float v0 = row[64 + c * 3 + 0];
            float v1 = row[64 + c * 3 + 1];
            float v2 = row[64 + c * 3 + 2];
            acc[a][0][0] += sv * ws0;  acc[a][1][0] += sv * ws1;
            acc[a][0][1] += v0 * wv0;  acc[a][1][1] += v0 * wv1;
            acc[a][0][2] += v1 * wv0;  acc[a][1][2] += v1 * wv1;
            acc[a][0][3] += v2 * wv0;  acc[a][1][3] += v2 * wv1;
        }
    }
#pragma unroll
    for (int a = 0; a < 4; a++) {
        int gn = n0 + nbase + a;
        if (gn >= NN) continue;
        ((float4*)g_pre)[(size_t)gn * 64 + kk] =
            make_float4(acc[a][0][0], acc[a][0][1], acc[a][0][2], acc[a][0][3]);
        ((float4*)g_pre)[(size_t)gn * 64 + kk + 32] =
            make_float4(acc[a][1][0], acc[a][1][1], acc[a][1][2], acc[a][1][3]);
        ((float4*)g_acc)[(size_t)gn * 64 + kk]      = make_float4(0.f, 0.f, 0.f, 0.f);
        ((float4*)g_acc)[(size_t)gn * 64 + kk + 32] = make_float4(0.f, 0.f, 0.f, 0.f);
    }
}

// ---------------------------------------------------------------------------
// Kernel B: edge kernel (persistent). 384 threads, 96 edges per tile.
// smem: W1 | W2slice | H(96x68) | Wbuf(5x96x68, slice0 doubles as EF) | Y | idx
// ---------------------------------------------------------------------------
#define EB   96
#define TB_B 384
#define NT_B ((EE + EB - 1) / EB)
#define SMEM_B_BYTES ((4096 + 4096 + 96*68 + 5*96*68 + 96*3) * 4 + 2 * 96 * 4)

__global__ void k_edge(const float* __restrict__ vectors,
                       const float* __restrict__ ef,
                       const int* __restrict__ eidx,
                       const float* __restrict__ W1,
                       const float* __restrict__ W2) {
    extern __shared__ float sm[];
    float* sW1  = sm;                    // 4096
    float* sW2s = sW1 + 4096;            // 4096
    float* sH   = sW2s + 4096;           // 96*68
    float* sWb  = sH + 96 * 68;          // 5*96*68 (slice0 aliases EF)
    float* sY   = sWb + 5 * 96 * 68;     // 288
    int*   sSnd = (int*)(sY + 288);      // 96
    int*   sRcv = sSnd + 96;             // 96

    int tid = threadIdx.x;
    const int* snd = eidx;
    const int* rcv = eidx + EE;

    for (int i = tid; i < 4096; i += TB_B) sW1[i] = W1[i];

    int tx = tid & 15;   // cols c = tx*4 .. tx*4+3
    int ty = tid >> 4;   // 0..23 ; rows e = ty + 24*r

    for (int tile = blockIdx.x; tile < NT_B; tile += gridDim.x) {
        int e0 = tile * EB;
        __syncthreads();   // prior epilogue done (and W1 load on iter 0)

        // stage edge feats into Wbuf slice 0
        for (int i = tid; i < EB * 16; i += TB_B) {
            int e = i >> 4, c4 = i & 15;
            int ge = e0 + e;
            float4 v = make_float4(0.f, 0.f, 0.f, 0.f);
            if (ge < EE) v = ((const float4*)ef)[(size_t)ge * 16 + c4];
            ((float4*)(sWb + e * 68))[c4] = v;
        }
        if (tid < EB) {
            int ge = e0 + tid;
            float vx = 0.f, vy = 0.f, vz = 0.f; int sn = 0, rc = 0;
            if (ge < EE) {
                vx = vectors[(size_t)ge * 3 + 0];
                vy = vectors[(size_t)ge * 3 + 1];
                vz = vectors[(size_t)ge * 3 + 2];
                sn = snd[ge]; rc = rcv[ge];
            }
            float nrm = sqrtf(vx * vx + vy * vy + vz * vz) + 1e-12f;
            float sc = 1.7320508075688772f / nrm;   // sqrt(3)/|r|
            sY[tid * 3 + 0] = vx * sc;
            sY[tid * 3 + 1] = vy * sc;
            sY[tid * 3 + 2] = vz * sc;
            sSnd[tid] = sn; sRcv[tid] = rc;
        }
        __syncthreads();

        // GEMM1: h = silu(ef @ W1), 4x4 micro-tile
        float hacc[4][4];
#pragma unroll
        for (int r = 0; r < 4; r++)
#pragma unroll
            for (int j = 0; j < 4; j++) hacc[r][j] = 0.f;
        for (int k = 0; k < 64; k++) {
            float4 b = ((const float4*)(sW1 + k * 64))[tx];
#pragma unroll
            for (int r = 0; r < 4; r++) {
                float a = sWb[(ty + 24 * r) * 68 + k];
                hacc[r][0] += a * b.x; hacc[r][1] += a * b.y;
                hacc[r][2] += a * b.z; hacc[r][3] += a * b.w;
            }
        }
#pragma unroll
        for (int r = 0; r < 4; r++) {
            int e = ty + 24 * r;
            ((float4*)(sH + e * 68))[tx] = make_float4(
                silu(hacc[r][0]), silu(hacc[r][1]), silu(hacc[r][2]), silu(hacc[r][3]));
        }
        __syncthreads();   // EF (slice0) now dead, H ready

        // GEMM2: 5 slices of W2 streamed through sW2s
        for (int j5 = 0; j5 < 5; j5++) {
            for (int i = tid; i < 1024; i += TB_B) {
                int k = i >> 4, c4 = i & 15;
                ((float4*)(sW2s + k * 64))[c4] =
                    ((const float4*)(W2 + (size_t)k * 320 + j5 * 64))[c4];
            }
            __syncthreads();
            float wacc[4][4];
#pragma unroll
            for (int r = 0; r < 4; r++)
#pragma unroll
                for (int j = 0; j < 4; j++) wacc[r][j] = 0.f;
            for (int k = 0; k < 64; k++) {
                float4 b = ((const float4*)(sW2s + k * 64))[tx];
#pragma unroll
                for (int r = 0; r < 4; r++) {
                    float a = sH[(ty + 24 * r) * 68 + k];
                    wacc[r][0] += a * b.x; wacc[r][1] += a * b.y;
                    wacc[r][2] += a * b.z; wacc[r][3] += a * b.w;
                }
            }
#pragma unroll
            for (int r = 0; r < 4; r++) {
                int e = ty + 24 * r;
                ((float4*)(sWb + (j5 * 96 + e) * 68))[tx] =
                    make_float4(wacc[r][0], wacc[r][1], wacc[r][2], wacc[r][3]);
            }
            __syncthreads();
        }

        // epilogue: build messages, vector scatter-add
#pragma unroll
        for (int it = 0; it < 16; it++) {
            int p = it * TB_B + tid;
            int e = p >> 6, c = p & 63;
            int ge = e0 + e;
            if (ge >= EE) continue;
            int sn = sSnd[e];
            float4 pre = ((const float4*)g_pre)[(size_t)sn * 64 + c];
            float Yx = sY[e * 3 + 0], Yy = sY[e * 3 + 1], Yz = sY[e * 3 + 2];
            float w0 = sWb[(0 * 96 + e) * 68 + c];
            float w1 = sWb[(1 * 96 + e) * 68 + c];
            float w2 = sWb[(2 * 96 + e) * 68 + c];
            float w3 = sWb[(3 * 96 + e) * 68 + c];
            float w4 = sWb[(4 * 96 + e) * 68 + c];
            float sj = pre.x, vx = pre.y, vy = pre.z, vz = pre.w;
            float vdY = vx * Yx + vy * Yy + vz * Yz;
            float ms = w0 * sj + w1 * vdY;
            float cx = vy * Yz - vz * Yy;
            float cy = vz * Yx - vx * Yz;
            float cz = vx * Yy - vy * Yx;
            float t = w2 * sj;
            float mvx = t * Yx + w3 * vx + w4 * cx;
            float mvy = t * Yy + w3 * vy + w4 * cy;
            float mvz = t * Yz + w3 * vz + w4 * cz;
            float4* dst = ((float4*)g_acc) + (size_t)sRcv[e] * 64 + c;
            asm volatile("red.global.add.v4.f32 [%0], {%1,%2,%3,%4};"
                         :: "l"(dst), "f"(ms), "f"(mvx), "f"(mvy), "f"(mvz)
                         : "memory");
        }
    }
}

// ---------------------------------------------------------------------------
// Kernel C: node post (persistent). 512 threads, 8 nodes/tile.
// thread: k = tid&63 (output channel), g = tid>>6 (node within tile)
// ---------------------------------------------------------------------------
#define NB   8
#define TB_C 512
#define NT_C (NN / NB)
#define SMEM_C_BYTES ((11 * 4096 + 64 + 64 + 512 + 1536 + 512 + 512 + 1536 + 512 + 512 + 32) * 4)

__global__ void k_post(const float* __restrict__ Wsp, const float* __restrict__ Wvp,
                       const float* __restrict__ Ps1w, const float* __restrict__ Ps2w,
                       const float* __restrict__ Ps3w, const float* __restrict__ Pvvw,
                       const float* __restrict__ Pv1w, const float* __restrict__ Pv2w,
                       const float* __restrict__ Pv3w, const float* __restrict__ Rw1,
                       const float* __restrict__ Rw2, const float* __restrict__ Rg,
                       const float* __restrict__ Rvm, float* __restrict__ out) {
    extern __shared__ float sm[];
    float* sWsp = sm + 0 * 4096;
    float* sWvp = sm + 1 * 4096;
    float* sPs1 = sm + 2 * 4096;
    float* sPs2 = sm + 3 * 4096;
    float* sPs3 = sm + 4 * 4096;
    float* sPvv = sm + 5 * 4096;
    float* sPv1 = sm + 6 * 4096;
    float* sPv2 = sm + 7 * 4096;
    float* sPv3 = sm + 8 * 4096;
    float* sRw1 = sm + 9 * 4096;
    float* sRw2 = sm + 10 * 4096;
    float* sRg  = sm + 11 * 4096;        // 64
    float* sRvm = sRg + 64;              // 64
    float* sRs  = sRvm + 64;             // 8*64
    float* sRv  = sRs + 512;             // 8*64*3 (reused as vmix staging)
    float* sAs  = sRv + 1536;            // 512
    float* sVv  = sAs + 512;             // 512
    float* sAv  = sVv + 512;             // 1536
    float* sPsb = sAv + 1536;            // 512
    float* sHr  = sPsb + 512;            // 512
    float* sVs  = sHr + 512;             // 32

    int tid = threadIdx.x;
    for (int i = tid; i < 4096; i += TB_C) {
        sWsp[i] = Wsp[i];  sWvp[i] = Wvp[i];
        sPs1[i] = Ps1w[i]; sPs2[i] = Ps2w[i]; sPs3[i] = Ps3w[i];
        sPvv[i] = Pvvw[i];
        sPv1[i] = Pv1w[i]; sPv2[i] = Pv2w[i]; sPv3[i] = Pv3w[i];
        sRw1[i] = Rw1[i];  sRw2[i] = Rw2[i];
    }
    if (tid < 64) { sRg[tid] = Rg[tid]; sRvm[tid] = Rvm[tid]; }

    int k = tid & 63;
    int g = tid >> 6;   // 0..7
    float* out_s  = out;
    float* out_v  = out + (size_t)NN * 64;
    float* out_nf = out + (size_t)NN * 67;

    for (int tile = blockIdx.x; tile < NT_C; tile += gridDim.x) {
        int gn = tile * NB + g;
        __syncthreads();   // weights visible (iter 0) / previous tile done

        // stage 1: load accumulated messages, scale by 1/16
        float4 r4 = ((const float4*)g_acc)[(size_t)gn * 64 + k];
        const float inv = 1.0f / 16.0f;
        sRs[g * 64 + k] = r4.x * inv;
        sRv[(g * 64 + k) * 3 + 0] = r4.y * inv;
        sRv[(g * 64 + k) * 3 + 1] = r4.z * inv;
        sRv[(g * 64 + k) * 3 + 2] = r4.w * inv;
        __syncthreads();

        // stage 2: a_s @ W_s_post, a_v @ W_v_post, vv
        float as = 0.f, av0 = 0.f, av1 = 0.f, av2 = 0.f;
        for (int c = 0; c < 64; c++) {
            float wsp = sWsp[c * 64 + k];
            float wvp = sWvp[c * 64 + k];
            float rs = sRs[g * 64 + c];
            float r0 = sRv[(g * 64 + c) * 3 + 0];
            float r1 = sRv[(g * 64 + c) * 3 + 1];
            float r2 = sRv[(g * 64 + c) * 3 + 2];
            as += rs * wsp; av0 += r0 * wvp; av1 += r1 * wvp; av2 += r2 * wvp;
        }
        sAs[g * 64 + k] = as;
        sAv[(g * 64 + k) * 3 + 0] = av0;
        sAv[(g * 64 + k) * 3 + 1] = av1;
        sAv[(g * 64 + k) * 3 + 2] = av2;
        sVv[g * 64 + k] = av0 * av0 + av1 * av1 + av2 * av2;
        __syncthreads();

        // stage 3: ps / pv polynomial mix
        float ps = 0.f, pv0 = 0.f, pv1 = 0.f, pv2 = 0.f;
        for (int c = 0; c < 64; c++) {
            float a = sAs[g * 64 + c];
            float a2 = a * a;
            float a3 = a2 * a;
            float vvc = sVv[g * 64 + c];
            ps += a * sPs1[c * 64 + k] + a2 * sPs2[c * 64 + k]
                + a3 * sPs3[c * 64 + k] + vvc * sPvv[c * 64 + k];
            float q = sPv1[c * 64 + k] + a * sPv2[c * 64 + k] + a2 * sPv3[c * 64 + k];
            pv0 += sAv[(g * 64 + c) * 3 + 0] * q;
            pv1 += sAv[(g * 64 + c) * 3 + 1] * q;
            pv2 += sAv[(g * 64 + c) * 3 + 2] * q;
        }
        sPsb[g * 64 + k] = ps;
        float rv = sRvm[k];
        sRv[(g * 64 + k) * 3 + 0] = pv0 * rv;   // reuse raw-v buffer as vmix staging
        sRv[(g * 64 + k) * 3 + 1] = pv1 * rv;
        sRv[(g * 64 + k) * 3 + 2] = pv2 * rv;
        out_nf[(size_t)gn * 256 + k] = ps;
        out_nf[(size_t)gn * 256 + 64 + k * 3 + 0] = pv0;
        out_nf[(size_t)gn * 256 + 64 + k * 3 + 1] = pv1;
        out_nf[(size_t)gn * 256 + 64 + k * 3 + 2] = pv2;
        __syncthreads();

        // stage 4: hr = silu(ps @ R_w1); vec partial reduce
        float hr = 0.f;
        for (int c = 0; c < 64; c++) hr += sPsb[g * 64 + c] * sRw1[c * 64 + k];
        hr = silu(hr);
        sHr[g * 64 + k] = hr;
        if (k < 3) {
            float s = 0.f;
            for (int c = 0; c < 64; c++) s += sRv[(g * 64 + c) * 3 + k];
            sVs[g * 4 + k] = s;
        }
        __syncthreads();

        // stage 5: out_s = hr @ R_w2, gate = silu(hr . R_gate), vec
        float os = 0.f, gs = 0.f;
        for (int m = 0; m < 64; m++) {
            float h = sHr[g * 64 + m];
            os += h * sRw2[m * 64 + k];
            gs += h * sRg[m];
        }
        out_s[(size_t)gn * 64 + k] = os;
        float gate = silu(gs);
        if (k < 3) out_v[(size_t)gn * 3 + k] = sVs[g * 4 + k] * gate;
    }
}

// ---------------------------------------------------------------------------
extern "C" void kernel_launch(void* const* d_in, const int* in_sizes, int n_in,
                              void* d_out, int out_size) {
    const float* vectors    = (const float*)d_in[0];
    // d_in[1] = lengths (unused by reference)
    const float* node_feats = (const float*)d_in[2];
    const float* edge_feats = (const float*)d_in[3];
    const int*   eidx       = (const int*)d_in[4];
    const float* Wsu        = (const float*)d_in[5];
    const float* Wvu        = (const float*)d_in[6];
    const float* W1         = (const float*)d_in[7];
    const float* W2         = (const float*)d_in[8];
    const float* Wsp        = (const float*)d_in[9];
    const float* Wvp        = (const float*)d_in[10];
    const float* Ps1        = (const float*)d_in[11];
    const float* Ps2        = (const float*)d_in[12];
    const float* Ps3        = (const float*)d_in[13];
    const float* Pvv        = (const float*)d_in[14];
    const float* Pv1        = (const float*)d_in[15];
    const float* Pv2        = (const float*)d_in[16];
    const float* Pv3        = (const float*)d_in[17];
    const float* Rw1        = (const float*)d_in[18];
    const float* Rw2        = (const float*)d_in[19];
    const float* Rg         = (const float*)d_in[20];
    const float* Rvm        = (const float*)d_in[21];
    float* out = (float*)d_out;

    const int SMEM_A_BYTES = (4096 + 4096 + 32 * 256) * 4;   // 64 KB
    cudaFuncSetAttribute(k_pre,  cudaFuncAttributeMaxDynamicSharedMemorySize, SMEM_A_BYTES);
    cudaFuncSetAttribute(k_edge, cudaFuncAttributeMaxDynamicSharedMemorySize, SMEM_B_BYTES);
    cudaFuncSetAttribute(k_post, cudaFuncAttributeMaxDynamicSharedMemorySize, SMEM_C_BYTES);

    k_pre<<<(NN + 31) / 32, 256, SMEM_A_BYTES>>>(node_feats, Wsu, Wvu);
    k_edge<<<148, TB_B, SMEM_B_BYTES>>>(vectors, edge_feats, eidx, W1, W2);
    k_post<<<148, TB_C, SMEM_C_BYTES>>>(Wsp, Wvp, Ps1, Ps2, Ps3, Pvv,
                                        Pv1, Pv2, Pv3, Rw1, Rw2, Rg, Rvm, out);
}

// round 7
// speedup vs baseline: 1.7947x; 1.7947x over previous
#include <cuda_runtime.h>
#include <cuda_bf16.h>
#include <math.h>
#include <stdint.h>

#define NN 50000
#define EE 800000

extern __shared__ char dynsm[];

// scratch: pre[n][c][4] = {s_up, v_up.x, v_up.y, v_up.z}
//          acc[n][c][4] = {sum m_s, sum m_v.xyz}
__device__ float g_pre[(size_t)NN * 64 * 4];
__device__ float g_acc[(size_t)NN * 64 * 4];

__device__ __forceinline__ float silu(float x) {
    return x * (1.0f / (1.0f + __expf(-x)));
}

// split a pair of floats into bf16 hi and lo packed u32s
__device__ __forceinline__ void split2(float a, float b, uint32_t& hi, uint32_t& lo) {
    __nv_bfloat16 ah = __float2bfloat16(a);
    __nv_bfloat16 bh = __float2bfloat16(b);
    __nv_bfloat16 al = __float2bfloat16(a - __bfloat162float(ah));
    __nv_bfloat16 bl = __float2bfloat16(b - __bfloat162float(bh));
    hi = ((uint32_t)__bfloat16_as_ushort(bh) << 16) | (uint32_t)__bfloat16_as_ushort(ah);
    lo = ((uint32_t)__bfloat16_as_ushort(bl) << 16) | (uint32_t)__bfloat16_as_ushort(al);
}

// m16n8k16 row.col bf16 -> f32 accum (baseline PTX, works on plain sm_103)
__device__ __forceinline__ void mma16816(float* d, const uint32_t* a, const uint32_t* b) {
    asm volatile("mma.sync.aligned.m16n8k16.row.col.f32.bf16.bf16.f32 "
                 "{%0,%1,%2,%3}, {%4,%5,%6,%7}, {%8,%9}, {%0,%1,%2,%3};"
                 : "+f"(d[0]), "+f"(d[1]), "+f"(d[2]), "+f"(d[3])
                 : "r"(a[0]), "r"(a[1]), "r"(a[2]), "r"(a[3]),
                   "r"(b[0]), "r"(b[1]));
}

#define APITCH 72   // bf16 elems per row (144 B) -> conflict-light fragment access

// A fragment: rows R+(l>>2), R+(l>>2)+8 ; k-cols k0+(l&3)*2 (+8)
__device__ __forceinline__ void lda_frag(uint32_t* a, const __nv_bfloat16* base,
                                         int R, int l, int k0) {
    int r = R + (l >> 2);
    int c = k0 + (l & 3) * 2;
    a[0] = *(const uint32_t*)(base + r * APITCH + c);
    a[1] = *(const uint32_t*)(base + (r + 8) * APITCH + c);
    a[2] = *(const uint32_t*)(base + r * APITCH + c + 8);
    a[3] = *(const uint32_t*)(base + (r + 8) * APITCH + c + 8);
}
// B fragment (col-major k x n): Wt stored [n][k]
__device__ __forceinline__ void ldb_frag(uint32_t* b, const __nv_bfloat16* base,
                                         int n0, int l, int k0) {
    int n = n0 + (l >> 2);
    int k = k0 + (l & 3) * 2;
    b[0] = *(const uint32_t*)(base + n * APITCH + k);
    b[1] = *(const uint32_t*)(base + n * APITCH + k + 8);
}

// ---------------------------------------------------------------------------
// Kernel A: node pre-transform + accumulator zeroing
// ---------------------------------------------------------------------------
__global__ void k_pre(const float* __restrict__ nf,
                      const float* __restrict__ Wsu,
                      const float* __restrict__ Wvu) {
    float* sm = (float*)dynsm;
    float* sWs  = sm;
    float* sWv  = sm + 4096;
    float* sRaw = sm + 8192;

    int tid = threadIdx.x;
    for (int i = tid; i < 4096; i += 256) { sWs[i] = Wsu[i]; sWv[i] = Wvu[i]; }

    int n0 = blockIdx.x * 32;
    for (int i = tid; i < 32 * 64; i += 256) {
        int nl = i >> 6, c4 = i & 63;
        int gn = n0 + nl;
        float4 v = make_float4(0.f, 0.f, 0.f, 0.f);
        if (gn < NN) v = ((const float4*)nf)[(size_t)gn * 64 + c4];
        ((float4*)(sRaw + nl * 256))[c4] = v;
    }
    __syncthreads();

    int kk = tid & 31;
    int g  = tid >> 5;
    int nbase = g * 4;

    float acc[4][2][4];
#pragma unroll
    for (int a = 0; a < 4; a++)
#pragma unroll
        for (int b = 0; b < 2; b++)
#pragma unroll
            for (int q = 0; q < 4; q++) acc[a][b][q] = 0.f;

    for (int c = 0; c < 64; c++) {
        float ws0 = sWs[c * 64 + kk], ws1 = sWs[c * 64 + kk + 32];
        float wv0 = sWv[c * 64 + kk], wv1 = sWv[c * 64 + kk + 32];
#pragma unroll
        for (int a = 0; a < 4; a++) {
            const float* row = sRaw + (nbase + a) * 256;
            float sv = row[c];
            float v0 = row[64 + c * 3 + 0];
            float v1 = row[64 + c * 3 + 1];
            float v2 = row[64 + c * 3 + 2];
            acc[a][0][0] += sv * ws0;  acc[a][1][0] += sv * ws1;
            acc[a][0][1] += v0 * wv0;  acc[a][1][1] += v0 * wv1;
            acc[a][0][2] += v1 * wv0;  acc[a][1][2] += v1 * wv1;
            acc[a][0][3] += v2 * wv0;  acc[a][1][3] += v2 * wv1;
        }
    }
#pragma unroll
    for (int a = 0; a < 4; a++) {
        int gn = n0 + nbase + a;
        if (gn >= NN) continue;
        ((float4*)g_pre)[(size_t)gn * 64 + kk] =
            make_float4(acc[a][0][0], acc[a][0][1], acc[a][0][2], acc[a][0][3]);
        ((float4*)g_pre)[(size_t)gn * 64 + kk + 32] =
            make_float4(acc[a][1][0], acc[a][1][1], acc[a][1][2], acc[a][1][3]);
        ((float4*)g_acc)[(size_t)gn * 64 + kk]      = make_float4(0.f, 0.f, 0.f, 0.f);
        ((float4*)g_acc)[(size_t)gn * 64 + kk + 32] = make_float4(0.f, 0.f, 0.f, 0.f);
    }
}

// ---------------------------------------------------------------------------
// Kernel B: edge kernel via mma.sync (HMMA). 256 thr = 8 warps; each warp
// independently processes 16-edge groups. Split-precision bf16 (3 passes).
// ---------------------------------------------------------------------------
// smem byte offsets
#define O_W1H 0u
#define O_W1L 9216u
#define O_W2H 18432u
#define O_W2L 64512u
#define O_AHI 110592u
#define O_ALO 129024u
#define O_HHI 147456u
#define O_HLO 165888u
#define O_Y   184320u
#define O_SND 185856u
#define O_RCV 186368u
#define SMEM_TC 186880u

#define NGRP (EE / 16)   // 50000

__global__ void __launch_bounds__(256, 1)
k_edge_mm(const float* __restrict__ vectors,
          const float* __restrict__ ef,
          const int* __restrict__ eidx,
          const float* __restrict__ W1,
          const float* __restrict__ W2) {
    char* sm = dynsm;
    __nv_bfloat16* W1H = (__nv_bfloat16*)(sm + O_W1H);
    __nv_bfloat16* W1L = (__nv_bfloat16*)(sm + O_W1L);
    __nv_bfloat16* W2H = (__nv_bfloat16*)(sm + O_W2H);
    __nv_bfloat16* W2L = (__nv_bfloat16*)(sm + O_W2L);
    __nv_bfloat16* AHI = (__nv_bfloat16*)(sm + O_AHI);
    __nv_bfloat16* ALO = (__nv_bfloat16*)(sm + O_ALO);
    __nv_bfloat16* HHI = (__nv_bfloat16*)(sm + O_HHI);
    __nv_bfloat16* HLO = (__nv_bfloat16*)(sm + O_HLO);
    float* sY   = (float*)(sm + O_Y);
    int*   sSnd = (int*)(sm + O_SND);
    int*   sRcv = (int*)(sm + O_RCV);

    int tid  = threadIdx.x;
    int warp = tid >> 5;
    int l    = tid & 31;

    // stage W1^T, W2^T (hi/lo) once
    for (int i = tid; i < 4096; i += 256) {
        int k = i >> 6, n = i & 63;
        float v = W1[i];
        __nv_bfloat16 vh = __float2bfloat16(v);
        W1H[n * APITCH + k] = vh;
        W1L[n * APITCH + k] = __float2bfloat16(v - __bfloat162float(vh));
    }
    for (int i = tid; i < 20480; i += 256) {
        int k = i / 320, j = i - k * 320;
        float v = W2[i];
        __nv_bfloat16 vh = __float2bfloat16(v);
        W2H[j * APITCH + k] = vh;
        W2L[j * APITCH + k] = __float2bfloat16(v - __bfloat162float(vh));
    }
    __syncthreads();

    const int* snd = eidx;
    const int* rcv = eidx + EE;
    int R = warp * 16;                 // this warp's row region
    int gw = blockIdx.x * 8 + warp;    // global warp id
    const int stride = 148 * 8;

    for (int grp = gw; grp < NGRP; grp += stride) {
        int e0 = grp * 16;

        // ---- stage 16 edges of EF, split hi/lo ----
        const float4* gsrc = (const float4*)(ef + (size_t)e0 * 64);
#pragma unroll
        for (int j = 0; j < 8; j++) {
            int idx4 = l + 32 * j;          // 0..255 float4s
            float4 f = gsrc[idx4];
            int idx = idx4 * 4;
            int e = idx >> 6, c = idx & 63;
            uint32_t h0, l0, h1, l1;
            split2(f.x, f.y, h0, l0);
            split2(f.z, f.w, h1, l1);
            *(uint2*)(AHI + (R + e) * APITCH + c) = make_uint2(h0, h1);
            *(uint2*)(ALO + (R + e) * APITCH + c) = make_uint2(l0, l1);
        }
        if (l < 16) {
            int ge = e0 + l;
            float vx = vectors[(size_t)ge * 3 + 0];
            float vy = vectors[(size_t)ge * 3 + 1];
            float vz = vectors[(size_t)ge * 3 + 2];
            float sc = 1.7320508075688772f /
                       (sqrtf(vx * vx + vy * vy + vz * vz) + 1e-12f);
            sY[(R + l) * 3 + 0] = vx * sc;
            sY[(R + l) * 3 + 1] = vy * sc;
            sY[(R + l) * 3 + 2] = vz * sc;
            sSnd[R + l] = snd[ge];
            sRcv[R + l] = rcv[ge];
        }
        __syncwarp();

        // ---- GEMM1: D1(16x64) = EF @ W1 (3-pass split) ----
        float d1[8][4];
#pragma unroll
        for (int n = 0; n < 8; n++)
#pragma unroll
            for (int q = 0; q < 4; q++) d1[n][q] = 0.f;
#pragma unroll
        for (int ks = 0; ks < 4; ks++) {
            int k0 = ks * 16;
            uint32_t ah[4], al[4];
            lda_frag(ah, AHI, R, l, k0);
            lda_frag(al, ALO, R, l, k0);
#pragma unroll
            for (int n = 0; n < 8; n++) {
                uint32_t bh[2], bl[2];
                ldb_frag(bh, W1H, n * 8, l, k0);
                ldb_frag(bl, W1L, n * 8, l, k0);
                mma16816(d1[n], ah, bh);
                mma16816(d1[n], ah, bl);
                mma16816(d1[n], al, bh);
            }
        }

        // ---- H = silu(D1), re-split into smem ----
        {
            int r = R + (l >> 2);
#pragma unroll
            for (int n = 0; n < 8; n++) {
                int c0 = n * 8 + (l & 3) * 2;
                uint32_t h, lo;
                split2(silu(d1[n][0]), silu(d1[n][1]), h, lo);
                *(uint32_t*)(HHI + r * APITCH + c0) = h;
                *(uint32_t*)(HLO + r * APITCH + c0) = lo;
                split2(silu(d1[n][2]), silu(d1[n][3]), h, lo);
                *(uint32_t*)(HHI + (r + 8) * APITCH + c0) = h;
                *(uint32_t*)(HLO + (r + 8) * APITCH + c0) = lo;
            }
        }
        __syncwarp();

        // ---- GEMM2 per 8-channel block + fused epilogue ----
#pragma unroll 1
        for (int n = 0; n < 8; n++) {
            float d2[5][4];
#pragma unroll
            for (int j = 0; j < 5; j++)
#pragma unroll
                for (int q = 0; q < 4; q++) d2[j][q] = 0.f;
#pragma unroll
            for (int ks = 0; ks < 4; ks++) {
                int k0 = ks * 16;
                uint32_t ah[4], al[4];
                lda_frag(ah, HHI, R, l, k0);
                lda_frag(al, HLO, R, l, k0);
#pragma unroll
                for (int j = 0; j < 5; j++) {
                    uint32_t bh[2], bl[2];
                    ldb_frag(bh, W2H, j * 64 + n * 8, l, k0);
                    ldb_frag(bl, W2L, j * 64 + n * 8, l, k0);
                    mma16816(d2[j], ah, bh);
                    mma16816(d2[j], ah, bl);
                    mma16816(d2[j], al, bh);
                }
            }
            // epilogue: rows l>>2 and l>>2+8, cols c0, c0+1
            int c0 = n * 8 + (l & 3) * 2;
#pragma unroll
            for (int half = 0; half < 2; half++) {
                int e = (l >> 2) + 8 * half;
                int sn = sSnd[R + e];
                int rc = sRcv[R + e];
                float Yx = sY[(R + e) * 3 + 0];
                float Yy = sY[(R + e) * 3 + 1];
                float Yz = sY[(R + e) * 3 + 2];
                const float4* preb = ((const float4*)g_pre) + (size_t)sn * 64;
                float4* accb = ((float4*)g_acc) + (size_t)rc * 64;
#pragma unroll
                for (int cc = 0; cc < 2; cc++) {
                    int c = c0 + cc;
                    float w0 = d2[0][2 * half + cc];
                    float w1 = d2[1][2 * half + cc];
                    float w2 = d2[2][2 * half + cc];
                    float w3 = d2[3][2 * half + cc];
                    float w4 = d2[4][2 * half + cc];
                    float4 pre = preb[c];
                    float sj = pre.x, vx = pre.y, vy = pre.z, vz = pre.w;
                    float vdY = vx * Yx + vy * Yy + vz * Yz;
                    float ms = w0 * sj + w1 * vdY;
                    float cx = vy * Yz - vz * Yy;
                    float cy = vz * Yx - vx * Yz;
                    float cz = vx * Yy - vy * Yx;
                    float t = w2 * sj;
                    float mvx = t * Yx + w3 * vx + w4 * cx;
                    float mvy = t * Yy + w3 * vy + w4 * cy;
                    float mvz = t * Yz + w3 * vz + w4 * cz;
                    float4* dst = accb + c;
                    asm volatile("red.global.add.v4.f32 [%0], {%1,%2,%3,%4};"
                                 :: "l"(dst), "f"(ms), "f"(mvx), "f"(mvy), "f"(mvz)
                                 : "memory");
                }
            }
        }
        __syncwarp();
    }
}

// ---------------------------------------------------------------------------
// Kernel C: node post (persistent)
// ---------------------------------------------------------------------------
#define NB   8
#define TB_C 512
#define NT_C (NN / NB)
#define SMEM_C_BYTES ((11 * 4096 + 64 + 64 + 512 + 1536 + 512 + 512 + 1536 + 512 + 512 + 32) * 4)

__global__ void k_post(const float* __restrict__ Wsp, const float* __restrict__ Wvp,
                       const float* __restrict__ Ps1w, const float* __restrict__ Ps2w,
                       const float* __restrict__ Ps3w, const float* __restrict__ Pvvw,
                       const float* __restrict__ Pv1w, const float* __restrict__ Pv2w,
                       const float* __restrict__ Pv3w, const float* __restrict__ Rw1,
                       const float* __restrict__ Rw2, const float* __restrict__ Rg,
                       const float* __restrict__ Rvm, float* __restrict__ out) {
    float* sm = (float*)dynsm;
    float* sWsp = sm + 0 * 4096;
    float* sWvp = sm + 1 * 4096;
    float* sPs1 = sm + 2 * 4096;
    float* sPs2 = sm + 3 * 4096;
    float* sPs3 = sm + 4 * 4096;
    float* sPvv = sm + 5 * 4096;
    float* sPv1 = sm + 6 * 4096;
    float* sPv2 = sm + 7 * 4096;
    float* sPv3 = sm + 8 * 4096;
    float* sRw1 = sm + 9 * 4096;
    float* sRw2 = sm + 10 * 4096;
    float* sRg  = sm + 11 * 4096;
    float* sRvm = sRg + 64;
    float* sRs  = sRvm + 64;
    float* sRv  = sRs + 512;
    float* sAs  = sRv + 1536;
    float* sVv  = sAs + 512;
    float* sAv  = sVv + 512;
    float* sPsb = sAv + 1536;
    float* sHr  = sPsb + 512;
    float* sVs  = sHr + 512;

    int tid = threadIdx.x;
    for (int i = tid; i < 4096; i += TB_C) {
        sWsp[i] = Wsp[i];  sWvp[i] = Wvp[i];
        sPs1[i] = Ps1w[i]; sPs2[i] = Ps2w[i]; sPs3[i] = Ps3w[i];
        sPvv[i] = Pvvw[i];
        sPv1[i] = Pv1w[i]; sPv2[i] = Pv2w[i]; sPv3[i] = Pv3w[i];
        sRw1[i] = Rw1[i];  sRw2[i] = Rw2[i];
    }
    if (tid < 64) { sRg[tid] = Rg[tid]; sRvm[tid] = Rvm[tid]; }

    int k = tid & 63;
    int g = tid >> 6;
    float* out_s  = out;
    float* out_v  = out + (size_t)NN * 64;
    float* out_nf = out + (size_t)NN * 67;

    for (int tile = blockIdx.x; tile < NT_C; tile += gridDim.x) {
        int gn = tile * NB + g;
        __syncthreads();

        float4 r4 = ((const float4*)g_acc)[(size_t)gn * 64 + k];
        const float inv = 1.0f / 16.0f;
        sRs[g * 64 + k] = r4.x * inv;
        sRv[(g * 64 + k) * 3 + 0] = r4.y * inv;
        sRv[(g * 64 + k) * 3 + 1] = r4.z * inv;
        sRv[(g * 64 + k) * 3 + 2] = r4.w * inv;
        __syncthreads();

        float as = 0.f, av0 = 0.f, av1 = 0.f, av2 = 0.f;
        for (int c = 0; c < 64; c++) {
            float wsp = sWsp[c * 64 + k];
            float wvp = sWvp[c * 64 + k];
            float rs = sRs[g * 64 + c];
            float r0 = sRv[(g * 64 + c) * 3 + 0];
            float r1 = sRv[(g * 64 + c) * 3 + 1];
            float r2 = sRv[(g * 64 + c) * 3 + 2];
            as += rs * wsp; av0 += r0 * wvp; av1 += r1 * wvp; av2 += r2 * wvp;
        }
        sAs[g * 64 + k] = as;
        sAv[(g * 64 + k) * 3 + 0] = av0;
        sAv[(g * 64 + k) * 3 + 1] = av1;
        sAv[(g * 64 + k) * 3 + 2] = av2;
        sVv[g * 64 + k] = av0 * av0 + av1 * av1 + av2 * av2;
        __syncthreads();

        float ps = 0.f, pv0 = 0.f, pv1 = 0.f, pv2 = 0.f;
        for (int c = 0; c < 64; c++) {
            float a = sAs[g * 64 + c];
            float a2 = a * a;
            float a3 = a2 * a;
            float vvc = sVv[g * 64 + c];
            ps += a * sPs1[c * 64 + k] + a2 * sPs2[c * 64 + k]
                + a3 * sPs3[c * 64 + k] + vvc * sPvv[c * 64 + k];
            float q = sPv1[c * 64 + k] + a * sPv2[c * 64 + k] + a2 * sPv3[c * 64 + k];
            pv0 += sAv[(g * 64 + c) * 3 + 0] * q;
            pv1 += sAv[(g * 64 + c) * 3 + 1] * q;
            pv2 += sAv[(g * 64 + c) * 3 + 2] * q;
        }
        sPsb[g * 64 + k] = ps;
        float rv = sRvm[k];
        sRv[(g * 64 + k) * 3 + 0] = pv0 * rv;
        sRv[(g * 64 + k) * 3 + 1] = pv1 * rv;
        sRv[(g * 64 + k) * 3 + 2] = pv2 * rv;
        out_nf[(size_t)gn * 256 + k] = ps;
        out_nf[(size_t)gn * 256 + 64 + k * 3 + 0] = pv0;
        out_nf[(size_t)gn * 256 + 64 + k * 3 + 1] = pv1;
        out_nf[(size_t)gn * 256 + 64 + k * 3 + 2] = pv2;
        __syncthreads();

        float hr = 0.f;
        for (int c = 0; c < 64; c++) hr += sPsb[g * 64 + c] * sRw1[c * 64 + k];
        hr = silu(hr);
        sHr[g * 64 + k] = hr;
        if (k < 3) {
            float s = 0.f;
            for (int c = 0; c < 64; c++) s += sRv[(g * 64 + c) * 3 + k];
            sVs[g * 4 + k] = s;
        }
        __syncthreads();

        float os = 0.f, gs = 0.f;
        for (int m = 0; m < 64; m++) {
            float h = sHr[g * 64 + m];
            os += h * sRw2[m * 64 + k];
            gs += h * sRg[m];
        }
        out_s[(size_t)gn * 64 + k] = os;
        float gate = silu(gs);
        if (k < 3) out_v[(size_t)gn * 3 + k] = sVs[g * 4 + k] * gate;
    }
}

// ---------------------------------------------------------------------------
extern "C" void kernel_launch(void* const* d_in, const int* in_sizes, int n_in,
                              void* d_out, int out_size) {
    const float* vectors    = (const float*)d_in[0];
    const float* node_feats = (const float*)d_in[2];
    const float* edge_feats = (const float*)d_in[3];
    const int*   eidx       = (const int*)d_in[4];
    const float* Wsu        = (const float*)d_in[5];
    const float* Wvu        = (const float*)d_in[6];
    const float* W1         = (const float*)d_in[7];
    const float* W2         = (const float*)d_in[8];
    const float* Wsp        = (const float*)d_in[9];
    const float* Wvp        = (const float*)d_in[10];
    const float* Ps1        = (const float*)d_in[11];
    const float* Ps2        = (const float*)d_in[12];
    const float* Ps3        = (const float*)d_in[13];
    const float* Pvv        = (const float*)d_in[14];
    const float* Pv1        = (const float*)d_in[15];
    const float* Pv2        = (const float*)d_in[16];
    const float* Pv3        = (const float*)d_in[17];
    const float* Rw1        = (const float*)d_in[18];
    const float* Rw2        = (const float*)d_in[19];
    const float* Rg         = (const float*)d_in[20];
    const float* Rvm        = (const float*)d_in[21];
    float* out = (float*)d_out;

    const int SMEM_A_BYTES = (4096 + 4096 + 32 * 256) * 4;
    cudaFuncSetAttribute(k_pre,     cudaFuncAttributeMaxDynamicSharedMemorySize, SMEM_A_BYTES);
    cudaFuncSetAttribute(k_edge_mm, cudaFuncAttributeMaxDynamicSharedMemorySize, SMEM_TC);
    cudaFuncSetAttribute(k_post,    cudaFuncAttributeMaxDynamicSharedMemorySize, SMEM_C_BYTES);

    k_pre<<<(NN + 31) / 32, 256, SMEM_A_BYTES>>>(node_feats, Wsu, Wvu);
    k_edge_mm<<<148, 256, SMEM_TC>>>(vectors, edge_feats, eidx, W1, W2);
    k_post<<<148, TB_C, SMEM_C_BYTES>>>(Wsp, Wvp, Ps1, Ps2, Ps3, Pvv,
                                        Pv1, Pv2, Pv3, Rw1, Rw2, Rg, Rvm, out);
}